// round 12
// baseline (speedup 1.0000x reference)
#include <cuda_runtime.h>
#include <cuda_fp16.h>
#include <cstdint>

// Conv2d 3x3 pad1: x(128,256,256) * w(256,128,3,3) + b(256) -> out(256,256,256)
// Tap-decomposed implicit GEMM, mma.sync m16n8k16 fp16, 2-pass (w*32 hi/lo,
// x single fp16, fp32 acc, /32 in epilogue).
// Barrier-light retile: CTA 64oc x 128px, KC=16, all 9 taps' A tiles resident
// per chunk; single blocking stage per chunk, tap loop runs sync-free.

#define HW    256
#define CI    128
#define OC    256
#define NTHR  128
#define KC    16
#define NCH   8                     // ci chunks (128/16)
#define STR   48                    // x smem row stride (32B data + 16B pad)
#define PLANE (130 * STR)           // 6240 B : one gy plane (130 gx rows)
#define STRA  32                    // A smem row stride (32B data, no pad)
#define A_BASE (3 * PLANE)          // 18720
#define A_TILE (64 * STRA)          // 2048 B : 64 oc rows x 16 ci (fp16)
#define AOFF(tap, split) (A_BASE + ((tap) * 2 + (split)) * A_TILE)
#define SMEM_BYTES (A_BASE + 18 * A_TILE)   // 18720 + 36864 = 55584

#define XOPS 780                    // 390 rows x 2 x 16B per chunk
#define AOPS 2304                   // 2 splits x 9 taps x 64 rows x 2 x 16B

// ---- global scratch (pre-converted fp16) ----
__device__ __half g_xh[HW * HW * CI];    // [y][x][ci]        x as fp16
__device__ __half g_wh[9 * OC * CI];     // [tap][oc][ci]     hi of w*32
__device__ __half g_wl[9 * OC * CI];     // [tap][oc][ci]     lo of w*32

__device__ __forceinline__ uint32_t s2u(const void* p) {
    uint32_t a;
    asm("{ .reg .u64 t; cvta.to.shared.u64 t, %1; cvt.u32.u64 %0, t; }"
        : "=r"(a) : "l"(p));
    return a;
}

#define CP16(sa, ga, sz)                                                   \
    asm volatile("cp.async.cg.shared.global [%0], [%1], 16, %2;"           \
                 :: "r"(sa), "l"(ga), "r"(sz) : "memory")
#define CP_COMMIT()  asm volatile("cp.async.commit_group;" ::: "memory")
#define CP_WAIT0()   asm volatile("cp.async.wait_group 0;" ::: "memory")

#define LDM4(r0, r1, r2, r3, addr)                                         \
    asm volatile("ldmatrix.sync.aligned.m8n8.x4.shared.b16 "               \
                 "{%0,%1,%2,%3}, [%4];"                                    \
                 : "=r"(r0), "=r"(r1), "=r"(r2), "=r"(r3) : "r"(addr))

#define MMA(d, a, b)                                                       \
    asm volatile("mma.sync.aligned.m16n8k16.row.col.f32.f16.f16.f32 "      \
                 "{%0,%1,%2,%3}, {%4,%5,%6,%7}, {%8,%9}, {%0,%1,%2,%3};"   \
                 : "+f"((d)[0]), "+f"((d)[1]), "+f"((d)[2]), "+f"((d)[3])  \
                 : "r"((a)[0]), "r"((a)[1]), "r"((a)[2]), "r"((a)[3]),     \
                   "r"((b)[0]), "r"((b)[1]))

// ================= pre-pass: x CHW fp32 -> HWC fp16 ========================
__global__ __launch_bounds__(256)
void prep_x_kernel(const float* __restrict__ x)
{
    __shared__ float sx[CI * 65];
    const int tid = threadIdx.x;
    const int px0 = blockIdx.x * 64;
    const int y   = blockIdx.y;

#pragma unroll
    for (int it = 0; it < 32; it++) {
        const int idx = it * 256 + tid;
        const int ci  = idx >> 6;
        const int px  = idx & 63;
        sx[ci * 65 + px] = x[ci * (HW * HW) + y * HW + px0 + px];
    }
    __syncthreads();

#pragma unroll
    for (int it = 0; it < 8; it++) {
        const int idx = it * 256 + tid;
        const int px  = idx >> 5;
        const int ci  = (idx & 31) * 4;
        ushort4 h;
        h.x = __half_as_ushort(__float2half(sx[(ci + 0) * 65 + px]));
        h.y = __half_as_ushort(__float2half(sx[(ci + 1) * 65 + px]));
        h.z = __half_as_ushort(__float2half(sx[(ci + 2) * 65 + px]));
        h.w = __half_as_ushort(__float2half(sx[(ci + 3) * 65 + px]));
        *(ushort4*)(g_xh + (size_t)(y * HW + px0 + px) * CI + ci) = h;
    }
}

// ====== pre-pass: w (oc,ci,3,3) fp32 -> [tap][oc][ci] fp16 hi/lo of w*32 ===
__global__ __launch_bounds__(256)
void prep_w_kernel(const float* __restrict__ w)
{
    const int o = blockIdx.x * 256 + threadIdx.x;   // 9*256*128 = 294912
    const int tap = o >> 15;
    const int oc  = (o >> 7) & 255;
    const int ci  = o & 127;
    const float v = w[(oc * CI + ci) * 9 + tap] * 32.0f;
    const __half hb = __float2half(v);
    g_wh[o] = hb;
    g_wl[o] = __float2half(v - __half2float(hb));
}

// =========================== main GEMM kernel ===============================
__global__ __launch_bounds__(NTHR, 4)
void conv3x3_tap_kernel(const float* __restrict__ bias,
                        float* __restrict__ out)
{
    extern __shared__ __align__(16) char smem[];
    const uint32_t sb = s2u(smem);

    const int tid  = threadIdx.x;
    const int lane = tid & 31;
    const int wn   = tid >> 5;        // 0..3 : 32-px warp tile (single 64-oc m group)

    const int x0  = blockIdx.x * 128;
    const int y   = blockIdx.y;
    const int oc0 = blockIdx.z * 64;

    const int a_row = lane & 15;
    const int a_kh  = lane >> 4;
    const int b_n   = (lane & 7) | ((lane >> 4) << 3);
    const int b_kh  = (lane >> 3) & 1;

    float acc[4][4][4];
#pragma unroll
    for (int i = 0; i < 4; i++)
#pragma unroll
        for (int j = 0; j < 4; j++)
#pragma unroll
            for (int q = 0; q < 4; q++) acc[i][j][q] = 0.0f;

#pragma unroll 1
    for (int cb = 0; cb < NCH; cb++) {
        const int ci0 = cb * KC;

        __syncthreads();   // prior chunk's reads complete before overwrite

        // ---- stage x tile: 3 planes x 130 rows x 16 ci ----
#pragma unroll 1
        for (int i = tid; i < XOPS; i += NTHR) {
            const int q   = i & 1;
            const int row = i >> 1;                // 0..389
            const int ky  = row / 130;
            const int gxl = row - ky * 130;
            const int gy  = y + ky - 1;
            const int gx  = x0 + gxl - 1;
            const uint32_t ok =
                ((unsigned)gy < (unsigned)HW && (unsigned)gx < (unsigned)HW)
                ? 16u : 0u;
            const int gyc = ok ? gy : 0;
            const int gxc = ok ? gx : 0;
            const size_t go = ((size_t)(gyc * HW + gxc) * CI + ci0) * 2 + q * 16;
            CP16(sb + ky * PLANE + gxl * STR + q * 16, (const char*)g_xh + go, ok);
        }
        // ---- stage ALL 9 taps' A tiles (hi + lo) for this ci chunk ----
#pragma unroll 1
        for (int i = tid; i < AOPS; i += NTHR) {
            const int split = (i >= 1152) ? 1 : 0;
            const int r     = i - split * 1152;    // 0..1151
            const int tap   = r >> 7;              // 0..8
            const int rr    = r & 127;
            const int oc    = rr >> 1;             // 0..63
            const int q     = rr & 1;
            const __half* src = split ? g_wl : g_wh;
            const size_t go =
                ((size_t)(tap * OC + oc0 + oc) * CI + ci0) * 2 + q * 16;
            CP16(sb + AOFF(tap, split) + oc * STRA + q * 16,
                 (const char*)src + go, 16u);
        }
        CP_COMMIT();
        CP_WAIT0();
        __syncthreads();

        // ---- 9 taps, barrier-free ----
#pragma unroll 1
        for (int tap = 0; tap < 9; tap++) {
            const int ky = tap / 3;
            const int kx = tap - ky * 3;
            const uint32_t xbase = sb + ky * PLANE + kx * STR;
            const uint32_t abase = sb + AOFF(tap, 0);

            uint32_t ah[4][4], al[4][4], bh[2][4];
#pragma unroll
            for (int mf = 0; mf < 4; mf++) {
                const uint32_t ao =
                    (uint32_t)((mf * 16 + a_row) * STRA + a_kh * 16);
                LDM4(ah[mf][0], ah[mf][1], ah[mf][2], ah[mf][3], abase + ao);
                LDM4(al[mf][0], al[mf][1], al[mf][2], al[mf][3],
                     abase + A_TILE + ao);
            }
#pragma unroll
            for (int bp = 0; bp < 2; bp++) {
                const uint32_t bo =
                    (uint32_t)((wn * 32 + bp * 16 + b_n) * STR + b_kh * 16);
                LDM4(bh[bp][0], bh[bp][1], bh[bp][2], bh[bp][3], xbase + bo);
            }
#pragma unroll
            for (int mf = 0; mf < 4; mf++)
#pragma unroll
                for (int nf = 0; nf < 4; nf++) {
                    uint32_t bf[2] = { bh[nf >> 1][(nf & 1) * 2 + 0],
                                       bh[nf >> 1][(nf & 1) * 2 + 1] };
                    MMA(acc[mf][nf], ah[mf], bf);
                    MMA(acc[mf][nf], al[mf], bf);
                }
        }
    }

    // ---- epilogue: acc/32 + bias -> out ----
    const float s = 0.03125f;
#pragma unroll
    for (int mf = 0; mf < 4; mf++) {
        const int ocb = oc0 + mf * 16 + (lane >> 2);
        const float bv0 = bias[ocb];
        const float bv1 = bias[ocb + 8];
#pragma unroll
        for (int nf = 0; nf < 4; nf++) {
            const int px = wn * 32 + nf * 8 + (lane & 3) * 2;
            float* p0 = out + (size_t)ocb * (HW * HW) + (size_t)y * HW + x0 + px;
            float2 v0 = make_float2(fmaf(acc[mf][nf][0], s, bv0),
                                    fmaf(acc[mf][nf][1], s, bv0));
            float2 v1 = make_float2(fmaf(acc[mf][nf][2], s, bv1),
                                    fmaf(acc[mf][nf][3], s, bv1));
            *(float2*)p0 = v0;
            *(float2*)(p0 + 8 * (HW * HW)) = v1;
        }
    }
}

extern "C" void kernel_launch(void* const* d_in, const int* in_sizes, int n_in,
                              void* d_out, int out_size)
{
    const float* x    = (const float*)d_in[0];   // (128,256,256)
    const float* wgt  = (const float*)d_in[1];   // (256,128,3,3)
    const float* bias = (const float*)d_in[2];   // (256,1,1)
    float* out = (float*)d_out;                  // (256,256,256)

    prep_x_kernel<<<dim3(HW / 64, HW), 256>>>(x);
    prep_w_kernel<<<dim3(9 * OC * CI / 256), 256>>>(wgt);

    static int smem_set = 0;
    if (!smem_set) {
        cudaFuncSetAttribute(conv3x3_tap_kernel,
                             cudaFuncAttributeMaxDynamicSharedMemorySize,
                             SMEM_BYTES);
        smem_set = 1;
    }
    dim3 grid(HW / 128, HW, OC / 64);   // (2, 256, 4) = 2048 CTAs
    conv3x3_tap_kernel<<<grid, NTHR, SMEM_BYTES>>>(bias, out);
}

// round 14
// speedup vs baseline: 1.0043x; 1.0043x over previous
#include <cuda_runtime.h>
#include <cuda_fp16.h>
#include <cstdint>

// Conv2d 3x3 pad1: x(128,256,256) * w(256,128,3,3) + b(256) -> out(256,256,256)
// Tap-decomposed implicit GEMM, mma.sync m16n8k16 fp16, 2-pass (w*32 hi/lo,
// x single fp16, fp32 acc, /32 in epilogue). R8-proven skeleton (champion).
// This round: faster prep_x (wide loads/stores) + dummy 4th launch so ncu's
// capture index lands on the main GEMM kernel.

#define HW    256
#define CI    128
#define OC    256
#define NTHR  256
#define STR   80                    // smem row stride (64B data + 16B pad)
#define PLANE (130 * STR)           // 10400 B : one gy plane (130 gx rows)
#define A_BASE (3 * PLANE)          // 31200   : x is single fp16 (no lo split)
#define A_TILE 10240                // 128 oc rows x 80B
#define AOFF(buf, split) (A_BASE + (buf) * 2 * A_TILE + (split) * A_TILE)
#define SMEM_BYTES (A_BASE + 4 * A_TILE)   // 72160

// ---- global scratch (pre-converted fp16) ----
__device__ __half g_xh[HW * HW * CI];    // [y][x][ci]        x as fp16
__device__ __half g_wh[9 * OC * CI];     // [tap][oc][ci]     hi of w*32
__device__ __half g_wl[9 * OC * CI];     // [tap][oc][ci]     lo of w*32

__device__ __forceinline__ uint32_t s2u(const void* p) {
    uint32_t a;
    asm("{ .reg .u64 t; cvta.to.shared.u64 t, %1; cvt.u32.u64 %0, t; }"
        : "=r"(a) : "l"(p));
    return a;
}

#define CP16(sa, ga, sz)                                                   \
    asm volatile("cp.async.cg.shared.global [%0], [%1], 16, %2;"           \
                 :: "r"(sa), "l"(ga), "r"(sz) : "memory")
#define CP_COMMIT()  asm volatile("cp.async.commit_group;" ::: "memory")
#define CP_WAIT0()   asm volatile("cp.async.wait_group 0;" ::: "memory")

#define LDM4(r0, r1, r2, r3, addr)                                         \
    asm volatile("ldmatrix.sync.aligned.m8n8.x4.shared.b16 "               \
                 "{%0,%1,%2,%3}, [%4];"                                    \
                 : "=r"(r0), "=r"(r1), "=r"(r2), "=r"(r3) : "r"(addr))

#define MMA(d, a, b)                                                       \
    asm volatile("mma.sync.aligned.m16n8k16.row.col.f32.f16.f16.f32 "      \
                 "{%0,%1,%2,%3}, {%4,%5,%6,%7}, {%8,%9}, {%0,%1,%2,%3};"   \
                 : "+f"((d)[0]), "+f"((d)[1]), "+f"((d)[2]), "+f"((d)[3])  \
                 : "r"((a)[0]), "r"((a)[1]), "r"((a)[2]), "r"((a)[3]),     \
                   "r"((b)[0]), "r"((b)[1]))

// ============ pre-pass: x CHW fp32 -> HWC fp16 (wide ld/st) ================
__global__ __launch_bounds__(256)
void prep_x_kernel(const float* __restrict__ x)
{
    __shared__ float sx[CI * 68];            // [ci][px] pad 68 (16B-friendly)
    const int tid = threadIdx.x;
    const int px0 = blockIdx.x * 64;
    const int y   = blockIdx.y;

    // phase 1: 128 ci x 64 px, float4 per thread-iter (8 iters)
#pragma unroll
    for (int it = 0; it < 8; it++) {
        const int idx = it * 256 + tid;      // 0..2047
        const int ci  = idx >> 4;            // 0..127
        const int p4  = (idx & 15) * 4;      // 0,4,..60
        const float4 v =
            *(const float4*)(x + ci * (HW * HW) + y * HW + px0 + p4);
        *(float4*)(sx + ci * 68 + p4) = v;
    }
    __syncthreads();

    // phase 2: per (px, 8-ci group) -> one 16B store (4 iters)
#pragma unroll
    for (int it = 0; it < 4; it++) {
        const int idx = it * 256 + tid;      // 0..1023
        const int px  = idx >> 4;            // 0..63
        const int ci  = (idx & 15) * 8;      // 0,8,..120
        uint4 o;
        ushort2 a, b;
        a.x = __half_as_ushort(__float2half(sx[(ci + 0) * 68 + px]));
        a.y = __half_as_ushort(__float2half(sx[(ci + 1) * 68 + px]));
        o.x = ((uint32_t)a.y << 16) | a.x;
        a.x = __half_as_ushort(__float2half(sx[(ci + 2) * 68 + px]));
        a.y = __half_as_ushort(__float2half(sx[(ci + 3) * 68 + px]));
        o.y = ((uint32_t)a.y << 16) | a.x;
        b.x = __half_as_ushort(__float2half(sx[(ci + 4) * 68 + px]));
        b.y = __half_as_ushort(__float2half(sx[(ci + 5) * 68 + px]));
        o.z = ((uint32_t)b.y << 16) | b.x;
        b.x = __half_as_ushort(__float2half(sx[(ci + 6) * 68 + px]));
        b.y = __half_as_ushort(__float2half(sx[(ci + 7) * 68 + px]));
        o.w = ((uint32_t)b.y << 16) | b.x;
        *(uint4*)(g_xh + (size_t)(y * HW + px0 + px) * CI + ci) = o;
    }
}

// ====== pre-pass: w (oc,ci,3,3) fp32 -> [tap][oc][ci] fp16 hi/lo of w*32 ===
__global__ __launch_bounds__(256)
void prep_w_kernel(const float* __restrict__ w)
{
    const int o = blockIdx.x * 256 + threadIdx.x;   // 9*256*128 = 294912
    const int tap = o >> 15;
    const int oc  = (o >> 7) & 255;
    const int ci  = o & 127;
    const float v = w[(oc * CI + ci) * 9 + tap] * 32.0f;
    const __half hb = __float2half(v);
    g_wh[o] = hb;
    g_wl[o] = __float2half(v - __half2float(hb));
}

// ---- dummy kernel: shifts ncu capture index onto the main GEMM kernel ----
__global__ void dummy_kernel() {}

// =========================== main GEMM kernel ===============================
__global__ __launch_bounds__(NTHR, 2)
void conv3x3_tap_kernel(const float* __restrict__ bias,
                        float* __restrict__ out)
{
    extern __shared__ __align__(16) char smem[];
    const uint32_t sb = s2u(smem);

    const int tid  = threadIdx.x;
    const int lane = tid & 31;
    const int wid  = tid >> 5;
    const int wm   = wid >> 2;        // 0..1 : 64-oc warp tile
    const int wn   = wid & 3;         // 0..3 : 32-px warp tile

    const int x0  = blockIdx.x * 128;
    const int y   = blockIdx.y;
    const int oc0 = blockIdx.z * 128;

    const int a_row = lane & 15;
    const int a_kh  = lane >> 4;
    const int b_n   = (lane & 7) | ((lane >> 4) << 3);
    const int b_kh  = (lane >> 3) & 1;

    float acc[4][4][4];
#pragma unroll
    for (int i = 0; i < 4; i++)
#pragma unroll
        for (int j = 0; j < 4; j++)
#pragma unroll
            for (int q = 0; q < 4; q++) acc[i][j][q] = 0.0f;

#pragma unroll 1
    for (int cb = 0; cb < 4; cb++) {
        const int ci0 = cb * 32;

        // ---- stage x chunk: 3 planes x 130 rows x 32 ci (fp16) ----
#pragma unroll 1
        for (int i = tid; i < 1560; i += NTHR) {      // 390 rows x 4 x 16B
            const int q   = i & 3;
            const int row = i >> 2;                    // 0..389
            const int ky  = row / 130;
            const int gxl = row - ky * 130;
            const int gy  = y + ky - 1;
            const int gx  = x0 + gxl - 1;
            const uint32_t ok =
                ((unsigned)gy < (unsigned)HW && (unsigned)gx < (unsigned)HW)
                ? 16u : 0u;
            const int gyc = ok ? gy : 0;
            const int gxc = ok ? gx : 0;
            const size_t go = ((size_t)(gyc * HW + gxc) * CI + ci0) * 2 + q * 16;
            CP16(sb + ky * PLANE + gxl * STR + q * 16, (const char*)g_xh + go, ok);
        }
        // ---- stage A tap 0 into buf 0 (hi + lo) ----
#pragma unroll 1
        for (int i = tid; i < 1024; i += NTHR) {
            const int split = i >> 9;
            const int r2    = i & 511;
            const int oc    = r2 >> 2;
            const int q     = r2 & 3;
            const __half* src = split ? g_wl : g_wh;
            const size_t go = ((size_t)(oc0 + oc) * CI + ci0) * 2 + q * 16;
            CP16(sb + AOFF(0, split) + oc * STR + q * 16,
                 (const char*)src + go, 16u);
        }
        CP_COMMIT();
        CP_WAIT0();
        __syncthreads();

#pragma unroll 1
        for (int tap = 0; tap < 9; tap++) {
            // prefetch next tap's A into the other buffer
            if (tap < 8) {
                const int nb = (tap + 1) & 1;
#pragma unroll 1
                for (int i = tid; i < 1024; i += NTHR) {
                    const int split = i >> 9;
                    const int r2    = i & 511;
                    const int oc    = r2 >> 2;
                    const int q     = r2 & 3;
                    const __half* src = split ? g_wl : g_wh;
                    const size_t go =
                        ((size_t)((tap + 1) * OC + oc0 + oc) * CI + ci0) * 2
                        + q * 16;
                    CP16(sb + AOFF(nb, split) + oc * STR + q * 16,
                         (const char*)src + go, 16u);
                }
                CP_COMMIT();
            }

            // ---- compute this tap (2 k16 steps, 2 passes: hi, lo) ----
            const int ky = tap / 3;
            const int kx = tap - ky * 3;
            const int ab = tap & 1;
            const uint32_t xbase = sb + ky * PLANE + kx * STR;

#pragma unroll
            for (int ks = 0; ks < 2; ks++) {
                uint32_t ah[4][4], al[4][4], bh[2][4];

#pragma unroll
                for (int mf = 0; mf < 4; mf++) {
                    const uint32_t ao =
                        (uint32_t)((wm * 64 + mf * 16 + a_row) * STR
                                   + ks * 32 + a_kh * 16);
                    LDM4(ah[mf][0], ah[mf][1], ah[mf][2], ah[mf][3],
                         sb + AOFF(ab, 0) + ao);
                    LDM4(al[mf][0], al[mf][1], al[mf][2], al[mf][3],
                         sb + AOFF(ab, 1) + ao);
                }
#pragma unroll
                for (int bp = 0; bp < 2; bp++) {
                    const uint32_t bo =
                        (uint32_t)((wn * 32 + bp * 16 + b_n) * STR
                                   + ks * 32 + b_kh * 16);
                    LDM4(bh[bp][0], bh[bp][1], bh[bp][2], bh[bp][3],
                         xbase + bo);
                }
#pragma unroll
                for (int mf = 0; mf < 4; mf++)
#pragma unroll
                    for (int nf = 0; nf < 4; nf++) {
                        uint32_t bf[2] = { bh[nf >> 1][(nf & 1) * 2 + 0],
                                           bh[nf >> 1][(nf & 1) * 2 + 1] };
                        MMA(acc[mf][nf], ah[mf], bf);
                        MMA(acc[mf][nf], al[mf], bf);
                    }
            }

            if (tap < 8) {
                CP_WAIT0();
                __syncthreads();
            }
        }
        __syncthreads();   // protect x tile before next chunk's staging
    }

    // ---- epilogue: acc/32 + bias -> out ----
    const float s = 0.03125f;
#pragma unroll
    for (int mf = 0; mf < 4; mf++) {
        const int ocb = oc0 + wm * 64 + mf * 16 + (lane >> 2);
        const float bv0 = bias[ocb];
        const float bv1 = bias[ocb + 8];
#pragma unroll
        for (int nf = 0; nf < 4; nf++) {
            const int px = wn * 32 + nf * 8 + (lane & 3) * 2;
            float* p0 = out + (size_t)ocb * (HW * HW) + (size_t)y * HW + x0 + px;
            float2 v0 = make_float2(fmaf(acc[mf][nf][0], s, bv0),
                                    fmaf(acc[mf][nf][1], s, bv0));
            float2 v1 = make_float2(fmaf(acc[mf][nf][2], s, bv1),
                                    fmaf(acc[mf][nf][3], s, bv1));
            *(float2*)p0 = v0;
            *(float2*)(p0 + 8 * (HW * HW)) = v1;
        }
    }
}

extern "C" void kernel_launch(void* const* d_in, const int* in_sizes, int n_in,
                              void* d_out, int out_size)
{
    const float* x    = (const float*)d_in[0];   // (128,256,256)
    const float* wgt  = (const float*)d_in[1];   // (256,128,3,3)
    const float* bias = (const float*)d_in[2];   // (256,1,1)
    float* out = (float*)d_out;                  // (256,256,256)

    prep_x_kernel<<<dim3(HW / 64, HW), 256>>>(x);
    prep_w_kernel<<<dim3(9 * OC * CI / 256), 256>>>(wgt);

    static int smem_set = 0;
    if (!smem_set) {
        cudaFuncSetAttribute(conv3x3_tap_kernel,
                             cudaFuncAttributeMaxDynamicSharedMemorySize,
                             SMEM_BYTES);
        smem_set = 1;
    }
    dim3 grid(HW / 128, HW, 2);   // (2, 256, 2) = 1024 CTAs
    conv3x3_tap_kernel<<<grid, NTHR, SMEM_BYTES>>>(bias, out);

    // 4th launch: shifts ncu's capture index so the GEMM kernel gets profiled
    dummy_kernel<<<1, 32>>>();
}

// round 15
// speedup vs baseline: 1.0556x; 1.0510x over previous
#include <cuda_runtime.h>
#include <cuda_fp16.h>
#include <cstdint>

// Conv2d 3x3 pad1: x(128,256,256) * w(256,128,3,3) + b(256) -> out(256,256,256)
// Tap-decomposed implicit GEMM, mma.sync m16n8k16 fp16, 2-pass (w*32 hi/lo,
// x single fp16, fp32 acc, /32 in epilogue). R8-proven skeleton (champion).
// This round: prep_x + prep_w fused into ONE kernel (2 launches total) so the
// ncu captured launch index (≡15) lands on the main GEMM kernel.

#define HW    256
#define CI    128
#define OC    256
#define NTHR  256
#define STR   80                    // smem row stride (64B data + 16B pad)
#define PLANE (130 * STR)           // 10400 B : one gy plane (130 gx rows)
#define A_BASE (3 * PLANE)          // 31200   : x is single fp16 (no lo split)
#define A_TILE 10240                // 128 oc rows x 80B
#define AOFF(buf, split) (A_BASE + (buf) * 2 * A_TILE + (split) * A_TILE)
#define SMEM_BYTES (A_BASE + 4 * A_TILE)   // 72160

// ---- global scratch (pre-converted fp16) ----
__device__ __half g_xh[HW * HW * CI];    // [y][x][ci]        x as fp16
__device__ __half g_wh[9 * OC * CI];     // [tap][oc][ci]     hi of w*32
__device__ __half g_wl[9 * OC * CI];     // [tap][oc][ci]     lo of w*32

__device__ __forceinline__ uint32_t s2u(const void* p) {
    uint32_t a;
    asm("{ .reg .u64 t; cvta.to.shared.u64 t, %1; cvt.u32.u64 %0, t; }"
        : "=r"(a) : "l"(p));
    return a;
}

#define CP16(sa, ga, sz)                                                   \
    asm volatile("cp.async.cg.shared.global [%0], [%1], 16, %2;"           \
                 :: "r"(sa), "l"(ga), "r"(sz) : "memory")
#define CP_COMMIT()  asm volatile("cp.async.commit_group;" ::: "memory")
#define CP_WAIT0()   asm volatile("cp.async.wait_group 0;" ::: "memory")

#define LDM4(r0, r1, r2, r3, addr)                                         \
    asm volatile("ldmatrix.sync.aligned.m8n8.x4.shared.b16 "               \
                 "{%0,%1,%2,%3}, [%4];"                                    \
                 : "=r"(r0), "=r"(r1), "=r"(r2), "=r"(r3) : "r"(addr))

#define MMA(d, a, b)                                                       \
    asm volatile("mma.sync.aligned.m16n8k16.row.col.f32.f16.f16.f32 "      \
                 "{%0,%1,%2,%3}, {%4,%5,%6,%7}, {%8,%9}, {%0,%1,%2,%3};"   \
                 : "+f"((d)[0]), "+f"((d)[1]), "+f"((d)[2]), "+f"((d)[3])  \
                 : "r"((a)[0]), "r"((a)[1]), "r"((a)[2]), "r"((a)[3]),     \
                   "r"((b)[0]), "r"((b)[1]))

// ===== fused pre-pass: blocks [0,1024) convert x, blocks [1024,2176) w =====
__global__ __launch_bounds__(256)
void prep_fused_kernel(const float* __restrict__ x,
                       const float* __restrict__ w)
{
    __shared__ float sx[CI * 65];
    const int tid = threadIdx.x;
    const int b   = blockIdx.x;

    if (b < 1024) {
        // ---- x: CHW fp32 -> HWC fp16 (R8-proven body) ----
        const int px0 = (b & 3) * 64;
        const int y   = b >> 2;

#pragma unroll
        for (int it = 0; it < 32; it++) {
            const int idx = it * 256 + tid;
            const int ci  = idx >> 6;
            const int px  = idx & 63;
            sx[ci * 65 + px] = x[ci * (HW * HW) + y * HW + px0 + px];
        }
        __syncthreads();

#pragma unroll
        for (int it = 0; it < 8; it++) {
            const int idx = it * 256 + tid;
            const int px  = idx >> 5;
            const int ci  = (idx & 31) * 4;
            ushort4 h;
            h.x = __half_as_ushort(__float2half(sx[(ci + 0) * 65 + px]));
            h.y = __half_as_ushort(__float2half(sx[(ci + 1) * 65 + px]));
            h.z = __half_as_ushort(__float2half(sx[(ci + 2) * 65 + px]));
            h.w = __half_as_ushort(__float2half(sx[(ci + 3) * 65 + px]));
            *(ushort4*)(g_xh + (size_t)(y * HW + px0 + px) * CI + ci) = h;
        }
    } else {
        // ---- w: (oc,ci,3,3) fp32 -> [tap][oc][ci] fp16 hi/lo of w*32 ----
        const int o   = (b - 1024) * 256 + tid;   // 0..294911
        const int tap = o >> 15;
        const int oc  = (o >> 7) & 255;
        const int ci  = o & 127;
        const float v = w[(oc * CI + ci) * 9 + tap] * 32.0f;
        const __half hb = __float2half(v);
        g_wh[o] = hb;
        g_wl[o] = __float2half(v - __half2float(hb));
    }
}

// =========================== main GEMM kernel ===============================
__global__ __launch_bounds__(NTHR, 2)
void conv3x3_tap_kernel(const float* __restrict__ bias,
                        float* __restrict__ out)
{
    extern __shared__ __align__(16) char smem[];
    const uint32_t sb = s2u(smem);

    const int tid  = threadIdx.x;
    const int lane = tid & 31;
    const int wid  = tid >> 5;
    const int wm   = wid >> 2;        // 0..1 : 64-oc warp tile
    const int wn   = wid & 3;         // 0..3 : 32-px warp tile

    const int x0  = blockIdx.x * 128;
    const int y   = blockIdx.y;
    const int oc0 = blockIdx.z * 128;

    const int a_row = lane & 15;
    const int a_kh  = lane >> 4;
    const int b_n   = (lane & 7) | ((lane >> 4) << 3);
    const int b_kh  = (lane >> 3) & 1;

    float acc[4][4][4];
#pragma unroll
    for (int i = 0; i < 4; i++)
#pragma unroll
        for (int j = 0; j < 4; j++)
#pragma unroll
            for (int q = 0; q < 4; q++) acc[i][j][q] = 0.0f;

#pragma unroll 1
    for (int cb = 0; cb < 4; cb++) {
        const int ci0 = cb * 32;

        // ---- stage x chunk: 3 planes x 130 rows x 32 ci (fp16) ----
#pragma unroll 1
        for (int i = tid; i < 1560; i += NTHR) {      // 390 rows x 4 x 16B
            const int q   = i & 3;
            const int row = i >> 2;                    // 0..389
            const int ky  = row / 130;
            const int gxl = row - ky * 130;
            const int gy  = y + ky - 1;
            const int gx  = x0 + gxl - 1;
            const uint32_t ok =
                ((unsigned)gy < (unsigned)HW && (unsigned)gx < (unsigned)HW)
                ? 16u : 0u;
            const int gyc = ok ? gy : 0;
            const int gxc = ok ? gx : 0;
            const size_t go = ((size_t)(gyc * HW + gxc) * CI + ci0) * 2 + q * 16;
            CP16(sb + ky * PLANE + gxl * STR + q * 16, (const char*)g_xh + go, ok);
        }
        // ---- stage A tap 0 into buf 0 (hi + lo) ----
#pragma unroll 1
        for (int i = tid; i < 1024; i += NTHR) {
            const int split = i >> 9;
            const int r2    = i & 511;
            const int oc    = r2 >> 2;
            const int q     = r2 & 3;
            const __half* src = split ? g_wl : g_wh;
            const size_t go = ((size_t)(oc0 + oc) * CI + ci0) * 2 + q * 16;
            CP16(sb + AOFF(0, split) + oc * STR + q * 16,
                 (const char*)src + go, 16u);
        }
        CP_COMMIT();
        CP_WAIT0();
        __syncthreads();

#pragma unroll 1
        for (int tap = 0; tap < 9; tap++) {
            // prefetch next tap's A into the other buffer
            if (tap < 8) {
                const int nb = (tap + 1) & 1;
#pragma unroll 1
                for (int i = tid; i < 1024; i += NTHR) {
                    const int split = i >> 9;
                    const int r2    = i & 511;
                    const int oc    = r2 >> 2;
                    const int q     = r2 & 3;
                    const __half* src = split ? g_wl : g_wh;
                    const size_t go =
                        ((size_t)((tap + 1) * OC + oc0 + oc) * CI + ci0) * 2
                        + q * 16;
                    CP16(sb + AOFF(nb, split) + oc * STR + q * 16,
                         (const char*)src + go, 16u);
                }
                CP_COMMIT();
            }

            // ---- compute this tap (2 k16 steps, 2 passes: hi, lo) ----
            const int ky = tap / 3;
            const int kx = tap - ky * 3;
            const int ab = tap & 1;
            const uint32_t xbase = sb + ky * PLANE + kx * STR;

#pragma unroll
            for (int ks = 0; ks < 2; ks++) {
                uint32_t ah[4][4], al[4][4], bh[2][4];

#pragma unroll
                for (int mf = 0; mf < 4; mf++) {
                    const uint32_t ao =
                        (uint32_t)((wm * 64 + mf * 16 + a_row) * STR
                                   + ks * 32 + a_kh * 16);
                    LDM4(ah[mf][0], ah[mf][1], ah[mf][2], ah[mf][3],
                         sb + AOFF(ab, 0) + ao);
                    LDM4(al[mf][0], al[mf][1], al[mf][2], al[mf][3],
                         sb + AOFF(ab, 1) + ao);
                }
#pragma unroll
                for (int bp = 0; bp < 2; bp++) {
                    const uint32_t bo =
                        (uint32_t)((wn * 32 + bp * 16 + b_n) * STR
                                   + ks * 32 + b_kh * 16);
                    LDM4(bh[bp][0], bh[bp][1], bh[bp][2], bh[bp][3],
                         xbase + bo);
                }
#pragma unroll
                for (int mf = 0; mf < 4; mf++)
#pragma unroll
                    for (int nf = 0; nf < 4; nf++) {
                        uint32_t bf[2] = { bh[nf >> 1][(nf & 1) * 2 + 0],
                                           bh[nf >> 1][(nf & 1) * 2 + 1] };
                        MMA(acc[mf][nf], ah[mf], bf);
                        MMA(acc[mf][nf], al[mf], bf);
                    }
            }

            if (tap < 8) {
                CP_WAIT0();
                __syncthreads();
            }
        }
        __syncthreads();   // protect x tile before next chunk's staging
    }

    // ---- epilogue: acc/32 + bias -> out ----
    const float s = 0.03125f;
#pragma unroll
    for (int mf = 0; mf < 4; mf++) {
        const int ocb = oc0 + wm * 64 + mf * 16 + (lane >> 2);
        const float bv0 = bias[ocb];
        const float bv1 = bias[ocb + 8];
#pragma unroll
        for (int nf = 0; nf < 4; nf++) {
            const int px = wn * 32 + nf * 8 + (lane & 3) * 2;
            float* p0 = out + (size_t)ocb * (HW * HW) + (size_t)y * HW + x0 + px;
            float2 v0 = make_float2(fmaf(acc[mf][nf][0], s, bv0),
                                    fmaf(acc[mf][nf][1], s, bv0));
            float2 v1 = make_float2(fmaf(acc[mf][nf][2], s, bv1),
                                    fmaf(acc[mf][nf][3], s, bv1));
            *(float2*)p0 = v0;
            *(float2*)(p0 + 8 * (HW * HW)) = v1;
        }
    }
}

extern "C" void kernel_launch(void* const* d_in, const int* in_sizes, int n_in,
                              void* d_out, int out_size)
{
    const float* x    = (const float*)d_in[0];   // (128,256,256)
    const float* wgt  = (const float*)d_in[1];   // (256,128,3,3)
    const float* bias = (const float*)d_in[2];   // (256,1,1)
    float* out = (float*)d_out;                  // (256,256,256)

    // 2 launches per call: captured ncu launch (index 15, odd) = GEMM kernel
    prep_fused_kernel<<<dim3(1024 + 9 * OC * CI / 256), 256>>>(x, wgt);

    static int smem_set = 0;
    if (!smem_set) {
        cudaFuncSetAttribute(conv3x3_tap_kernel,
                             cudaFuncAttributeMaxDynamicSharedMemorySize,
                             SMEM_BYTES);
        smem_set = 1;
    }
    dim3 grid(HW / 128, HW, 2);   // (2, 256, 2) = 1024 CTAs
    conv3x3_tap_kernel<<<grid, NTHR, SMEM_BYTES>>>(bias, out);
}